// round 13
// baseline (speedup 1.0000x reference)
#include <cuda_runtime.h>

// Problem constants
#define H_ 256
#define W_ 704
#define HW_ (H_ * W_)          // 180224 = 704 * 256
#define HW4_ (HW_ / 4)         // 45056 = 176 * 256
#define CIMG_ 256
#define NB_GATED 704           // 176 pixel tiles x 4 channel groups
#define NB_ZERO 352            // 352*256 threads x float4 = 2*HW floats

// Scratch (device globals — allocation is forbidden)
// g_GS[0..HW)      = gated scalar image accumulator (atomic partials)
// g_GS[HW..2*HW)   = sparse voxel logit accumulator (atomic)
__device__ float g_GS[2 * HW_];
__device__ float g_M2p[9 * 144];    // W2 rows, padded to 144 (K=131)
__device__ float g_M0p[9 * 36];     // M0 rows, padded to 36  (K=35)
__device__ float g_M1p[9 * 72];     // M1 rows, padded to 72  (K=67)
__device__ float g_swsum[9];
__device__ float g_ct[9];

// ---------------------------------------------------------------------------
// prep+zero: block 0 folds ALL weights (latency-engineered single block);
// blocks 1..352 zero g_GS.
// Block 0 plan:
//   - all threads: stage spw (sp_w) into smem
//   - threads 0..143: W2 columns via coalesced rd2_w row loads, 9 reg accums
//   - threads 144..255 (separate warps, overlap for free): linear prefetch of
//     rd0_w / rd1_w / biases into smem
//   - sync; stage C: M0/M1/M2 + swsum/ct entirely from smem
// ---------------------------------------------------------------------------
#define SPW_OFF  0
#define R0_OFF   1184                 // 1179 rounded up
#define R1_OFF   (R0_OFF + 4585)      // 131*35
#define B2_OFF   (R1_OFF + 8777)      // 131*67
#define B0_OFF   (B2_OFF + 131)
#define B1_OFF   (B0_OFF + 131)
#define W2_OFF   (B1_OFF + 131)
#define PREP_SMEM_FLOATS (W2_OFF + 9 * 144)   // 16235 floats = ~63.4 KB
#define PREP_SMEM_BYTES  (PREP_SMEM_FLOATS * 4)

__global__ void prep_zero_kernel(const float* __restrict__ sp_w,   // (131,9)
                                 const float* __restrict__ rd2_w,  // (131,131)
                                 const float* __restrict__ rd2_b,  // (131)
                                 const float* __restrict__ rd0_w,  // (131,35)
                                 const float* __restrict__ rd0_b,  // (131)
                                 const float* __restrict__ rd1_w,  // (131,67)
                                 const float* __restrict__ rd1_b,  // (131)
                                 const float* __restrict__ rd3_b) {
    if (blockIdx.x > 0) {
        int i = (blockIdx.x - 1) * 256 + threadIdx.x;  // 352*256 = 2*HW/4
        ((float4*)g_GS)[i] = make_float4(0.f, 0.f, 0.f, 0.f);
        return;
    }

    extern __shared__ float dyn[];
    float* spw = dyn + SPW_OFF;   // [c*9 + t]
    float* r0s = dyn + R0_OFF;    // rd0_w linear
    float* r1s = dyn + R1_OFF;    // rd1_w linear
    float* b2s = dyn + B2_OFF;
    float* b0s = dyn + B0_OFF;
    float* b1s = dyn + B1_OFF;
    float* w2s = dyn + W2_OFF;    // [t*144 + j], pads zero

    int tid = threadIdx.x;

    for (int i = tid; i < 1179; i += 256) spw[i] = sp_w[i];
    __syncthreads();

    if (tid < 144) {
        // Stage B: W2 column tid, coalesced row loads of rd2_w
        float acc[9];
#pragma unroll
        for (int t = 0; t < 9; t++) acc[t] = 0.f;
        if (tid < 131) {
#pragma unroll 8
            for (int c = 0; c < 131; c++) {
                float val = rd2_w[c * 131 + tid];
#pragma unroll
                for (int t = 0; t < 9; t++)
                    acc[t] = fmaf(spw[c * 9 + t], val, acc[t]);
            }
        }
#pragma unroll
        for (int t = 0; t < 9; t++) w2s[t * 144 + tid] = acc[t];  // pads = 0
    } else {
        // Prefetch warps: linear, coalesced copies into smem
        int c = tid - 144;  // 0..111
#pragma unroll 4
        for (int i = c; i < 4585; i += 112) r0s[i] = rd0_w[i];
#pragma unroll 4
        for (int i = c; i < 8777; i += 112) r1s[i] = rd1_w[i];
        if (c < 112) {
            for (int i = c; i < 131; i += 112) {
                b2s[i] = rd2_b[i];
                b0s[i] = rd0_b[i];
                b1s[i] = rd1_b[i];
            }
        }
    }
    __syncthreads();

    // Stage C: all from smem.
    // M0 (9 x 36, k<35 real)
    for (int idx = tid; idx < 324; idx += 256) {
        int t = idx / 36, k = idx - t * 36;
        float acc = 0.f;
        if (k < 35) {
#pragma unroll 8
            for (int j = 0; j < 131; j++)
                acc = fmaf(w2s[t * 144 + j], r0s[j * 35 + k], acc);
        }
        g_M0p[idx] = acc;
    }
    // M1 (9 x 72, k<67 real)
    for (int idx = tid; idx < 648; idx += 256) {
        int t = idx / 72, k = idx - t * 72;
        float acc = 0.f;
        if (k < 67) {
#pragma unroll 8
            for (int j = 0; j < 131; j++)
                acc = fmaf(w2s[t * 144 + j], r1s[j * 67 + k], acc);
        }
        g_M1p[idx] = acc;
    }
    // M2 = W2 (pads already zero in w2s)
    for (int idx = tid; idx < 1296; idx += 256) g_M2p[idx] = w2s[idx];

    // swsum / ct per tap (9 threads; smem-only loops)
    if (tid < 9) {
        float s = 0.f, cb = 0.f;
#pragma unroll 4
        for (int c = 0; c < 131; c++) {
            float w = spw[c * 9 + tid];
            s += w;
            cb = fmaf(w, b2s[c], cb);
        }
        float acc = 0.f;
#pragma unroll 4
        for (int j = 0; j < 131; j++)
            acc = fmaf(w2s[tid * 144 + j], b0s[j] + b1s[j], acc);
        g_swsum[tid] = s;
        g_ct[tid] = cb + acc + s * rd3_b[0];  // rd3 bias folded through taps
    }
}

// ---------------------------------------------------------------------------
// gated body: 64-channel partial of G(p), atomic accumulate.
// ---------------------------------------------------------------------------
__device__ __forceinline__ void gated_body(int b, const float* __restrict__ img,
                                           const float* __restrict__ w,
                                           float* sm) {
    int c0 = (b / 176) * 64;
    if (threadIdx.x < 64) sm[threadIdx.x] = w[c0 + threadIdx.x];
    __syncthreads();

    int p4 = (b % 176) * 256 + threadIdx.x;
    const float4* img4 = (const float4*)img + (size_t)c0 * HW4_;
    float4 acc = make_float4(0.f, 0.f, 0.f, 0.f);
#pragma unroll 8
    for (int c = 0; c < 64; c++) {
        float4 v = img4[(size_t)c * HW4_ + p4];
        float wc = sm[c];
        acc.x = fmaf(wc, v.x, acc.x);
        acc.y = fmaf(wc, v.y, acc.y);
        acc.z = fmaf(wc, v.z, acc.z);
        acc.w = fmaf(wc, v.w, acc.w);
    }
    atomicAdd(&g_GS[4 * p4 + 0], acc.x);
    atomicAdd(&g_GS[4 * p4 + 1], acc.y);
    atomicAdd(&g_GS[4 * p4 + 2], acc.z);
    atomicAdd(&g_GS[4 * p4 + 3], acc.w);
}

// ---------------------------------------------------------------------------
// scatter body: G lanes per voxel-group, VPG=2 voxels per group.
// ---------------------------------------------------------------------------
template <int G, int CHN, int LVL>
__device__ __forceinline__ void scatter_body(int b,
                                             const float* __restrict__ feat,
                                             const float* __restrict__ coord,
                                             const int* __restrict__ grid,
                                             int N, float* Ms) {
    constexpr int KP = G * 9;
    constexpr int RES = (9 + G - 1) / G;
    constexpr int VPG = 2;
    constexpr int GROUPS = 256 / G;
    const float* Mglob = (LVL == 0) ? g_M0p : (LVL == 1) ? g_M1p : g_M2p;

    for (int i = threadIdx.x; i < 9 * KP; i += 256) Ms[i] = Mglob[i];
    __syncthreads();

    int lane = threadIdx.x & 31;
    int g = lane & (G - 1);
    int v0 = (b * GROUPS + (int)(threadIdx.x / G)) * VPG;

    float4 e0[VPG], e1[VPG];
    float ec[VPG];
    int cx[VPG], cy[VPG];
    bool act[VPG];
#pragma unroll
    for (int j = 0; j < VPG; j++) {
        int v = v0 + j;
        act[j] = v < N;
        e0[j] = make_float4(0.f, 0.f, 0.f, 0.f);
        e1[j] = make_float4(0.f, 0.f, 0.f, 0.f);
        ec[j] = 0.f;
        cx[j] = 0;
        cy[j] = 0;
        if (act[j]) {
            const float4* f4 = (const float4*)(feat + (size_t)v * CHN + 8 * g);
            e0[j] = f4[0];
            e1[j] = f4[1];
            if (g < 3) ec[j] = coord[(size_t)v * 3 + g];
            cx[j] = grid[2 * v];
            cy[j] = grid[2 * v + 1];
        }
    }

    float res[VPG][RES];
#pragma unroll
    for (int j = 0; j < VPG; j++)
#pragma unroll
        for (int i = 0; i < RES; i++) res[j][i] = 0.f;

#pragma unroll
    for (int t = 0; t < 9; t++) {
        const float* Mrow = Ms + t * KP;
        const float4* M4 = (const float4*)(Mrow + 8 * g);
        float4 m0 = M4[0];
        float4 m1 = M4[1];
        float mc = Mrow[CHN + g];
        float s[VPG];
#pragma unroll
        for (int j = 0; j < VPG; j++) {
            float sj = ec[j] * mc;
            sj = fmaf(m0.x, e0[j].x, sj);
            sj = fmaf(m0.y, e0[j].y, sj);
            sj = fmaf(m0.z, e0[j].z, sj);
            sj = fmaf(m0.w, e0[j].w, sj);
            sj = fmaf(m1.x, e1[j].x, sj);
            sj = fmaf(m1.y, e1[j].y, sj);
            sj = fmaf(m1.z, e1[j].z, sj);
            sj = fmaf(m1.w, e1[j].w, sj);
            s[j] = sj;
        }
#pragma unroll
        for (int o = G / 2; o > 0; o >>= 1) {
#pragma unroll
            for (int j = 0; j < VPG; j++)
                s[j] += __shfl_xor_sync(0xffffffffu, s[j], o);
        }
        if (g == t % G) {
#pragma unroll
            for (int j = 0; j < VPG; j++) res[j][t / G] = s[j];
        }
    }

#pragma unroll
    for (int j = 0; j < VPG; j++) {
        if (act[j]) {
#pragma unroll
            for (int i = 0; i < RES; i++) {
                int t = i * G + g;
                if (t < 9) {
                    int py = cy[j] + 1 - t / 3;
                    int px = cx[j] + 1 - t % 3;
                    if (py >= 0 && py < H_ && px >= 0 && px < W_)
                        atomicAdd(&g_GS[HW_ + py * W_ + px], res[j][i]);
                }
            }
        }
    }
}

// ---------------------------------------------------------------------------
// fused mid: gated (DRAM-bound) + 3 voxel scatters (issue-bound), gated
// interleaved 1-in-6 through the block range.
// ---------------------------------------------------------------------------
__global__ void fused_mid_kernel(const float* __restrict__ img,
                                 const float* __restrict__ rd3_w,
                                 const float* __restrict__ vf0,
                                 const float* __restrict__ vc0,
                                 const int* __restrict__ g0, int N0, int B0,
                                 const float* __restrict__ vf1,
                                 const float* __restrict__ vc1,
                                 const int* __restrict__ g1, int N1, int B1,
                                 const float* __restrict__ vf2,
                                 const float* __restrict__ vc2,
                                 const int* __restrict__ g2, int N2, int SC) {
    __shared__ float sm[9 * 144];
    int b = blockIdx.x;
    int sb;
    if (b < 6 * NB_GATED) {
        int q = b / 6, r = b - q * 6;
        if (r == 0) { gated_body(q, img, rd3_w, sm); return; }
        sb = q * 5 + r - 1;
    } else {
        sb = 5 * NB_GATED + (b - 6 * NB_GATED);
    }
    if (sb >= SC) return;
    if (sb < B0) { scatter_body<4, 32, 0>(sb, vf0, vc0, g0, N0, sm); return; }
    sb -= B0;
    if (sb < B1) { scatter_body<8, 64, 1>(sb, vf1, vc1, g1, N1, sm); return; }
    sb -= B1;
    scatter_body<16, 128, 2>(sb, vf2, vc2, g2, N2, sm);
}

// ---------------------------------------------------------------------------
// final: out[c,p] = img[c,p] * sigmoid(L(p)), sigmoid computed inline from
// g_GS (9-tap halo + sparse term). grid (176,16).
// ---------------------------------------------------------------------------
__global__ void final_kernel(const float* __restrict__ img,
                             float* __restrict__ out,
                             const float* __restrict__ sp_b) {
    __shared__ float ssw[9], sct[9];
    __shared__ float sspb;
    if (threadIdx.x < 9) {
        ssw[threadIdx.x] = g_swsum[threadIdx.x];
        sct[threadIdx.x] = g_ct[threadIdx.x];
    }
    if (threadIdx.x == 9) sspb = sp_b[0];
    __syncthreads();

    int p4 = blockIdx.x * 256 + threadIdx.x;
    int c0 = blockIdx.y * 16;

    float sig[4];
#pragma unroll
    for (int u = 0; u < 4; u++) {
        int p = 4 * p4 + u;
        int y = p / W_, x = p - y * W_;
        float L = sspb + g_GS[HW_ + p];
#pragma unroll
        for (int t = 0; t < 9; t++) {
            int qy = y + t / 3 - 1;
            int qx = x + t % 3 - 1;
            if (qy >= 0 && qy < H_ && qx >= 0 && qx < W_)
                L = fmaf(ssw[t], g_GS[qy * W_ + qx], L + sct[t]);
        }
        sig[u] = 1.f / (1.f + __expf(-L));
    }

    const float4* i4 = (const float4*)img + (size_t)c0 * HW4_ + p4;
    float4* o4 = (float4*)out + (size_t)c0 * HW4_ + p4;
#pragma unroll
    for (int c = 0; c < 16; c++) {
        float4 v = i4[(size_t)c * HW4_];
        float4 o;
        o.x = v.x * sig[0];
        o.y = v.y * sig[1];
        o.z = v.z * sig[2];
        o.w = v.w * sig[3];
        o4[(size_t)c * HW4_] = o;
    }
}

// ---------------------------------------------------------------------------
// Launch
// ---------------------------------------------------------------------------
extern "C" void kernel_launch(void* const* d_in, const int* in_sizes, int n_in,
                              void* d_out, int out_size) {
    const float* img   = (const float*)d_in[0];
    const float* vf0   = (const float*)d_in[1];
    const float* vc0   = (const float*)d_in[2];
    const int*   g0    = (const int*)  d_in[3];
    const float* vf1   = (const float*)d_in[4];
    const float* vc1   = (const float*)d_in[5];
    const int*   g1    = (const int*)  d_in[6];
    const float* vf2   = (const float*)d_in[7];
    const float* vc2   = (const float*)d_in[8];
    const int*   g2    = (const int*)  d_in[9];
    const float* rd0_w = (const float*)d_in[10];
    const float* rd0_b = (const float*)d_in[11];
    const float* rd1_w = (const float*)d_in[12];
    const float* rd1_b = (const float*)d_in[13];
    const float* rd2_w = (const float*)d_in[14];
    const float* rd2_b = (const float*)d_in[15];
    const float* rd3_w = (const float*)d_in[16];
    const float* rd3_b = (const float*)d_in[17];
    const float* sp_w  = (const float*)d_in[18];
    const float* sp_b  = (const float*)d_in[19];

    int N0 = in_sizes[3] / 2;
    int N1 = in_sizes[6] / 2;
    int N2 = in_sizes[9] / 2;
    // VPG=2: voxels per block = 2 * (256/G)
    int B0 = (N0 + 127) / 128;   // G=4  -> 128 voxels/block
    int B1 = (N1 + 63) / 64;     // G=8  -> 64 voxels/block
    int B2 = (N2 + 31) / 32;     // G=16 -> 32 voxels/block
    int SC = B0 + B1 + B2;

    static bool attr_done = false;
    if (!attr_done) {
        cudaFuncSetAttribute(prep_zero_kernel,
                             cudaFuncAttributeMaxDynamicSharedMemorySize,
                             PREP_SMEM_BYTES);
        attr_done = true;
    }

    prep_zero_kernel<<<1 + NB_ZERO, 256, PREP_SMEM_BYTES>>>(
        sp_w, rd2_w, rd2_b, rd0_w, rd0_b, rd1_w, rd1_b, rd3_b);

    fused_mid_kernel<<<NB_GATED + SC, 256>>>(
        img, rd3_w,
        vf0, vc0, g0, N0, B0,
        vf1, vc1, g1, N1, B1,
        vf2, vc2, g2, N2, SC);

    final_kernel<<<dim3(HW4_ / 256, 16), 256>>>(img, (float*)d_out, sp_b);
}

// round 14
// speedup vs baseline: 1.0048x; 1.0048x over previous
#include <cuda_runtime.h>

// Problem constants
#define H_ 256
#define W_ 704
#define HW_ (H_ * W_)          // 180224 = 704 * 256
#define HW4_ (HW_ / 4)         // 45056 = 176 * 256
#define CIMG_ 256
#define NB_GATED 704           // 176 pixel tiles x 4 channel groups
#define NB_ZERO 352            // 352*256 threads x float4 = 2*HW floats

// Scratch (device globals — allocation is forbidden)
// g_GS[0..HW)      = gated scalar image accumulator (atomic partials)
// g_GS[HW..2*HW)   = sparse voxel logit accumulator (atomic)
__device__ float g_GS[2 * HW_];
__device__ float g_M2p[9 * 144];    // W2 rows, padded to 144 (K=131)
__device__ float g_M0p[9 * 36];     // M0 rows, padded to 36  (K=35)
__device__ float g_M1p[9 * 72];     // M1 rows, padded to 72  (K=67)
__device__ float g_swsum[9];
__device__ float g_ct[9];

// ---------------------------------------------------------------------------
// prep+zero: block 0 folds ALL weights (latency-engineered single block);
// blocks 1..352 zero g_GS.
// Block 0 plan:
//   - all threads: stage spw (sp_w) into smem
//   - threads 0..143: W2 columns via coalesced rd2_w row loads, 9 reg accums
//   - threads 144..255 (separate warps, overlap for free): linear prefetch of
//     rd0_w / rd1_w / biases into smem
//   - sync; stage C: M0/M1/M2 + swsum/ct entirely from smem
// ---------------------------------------------------------------------------
#define SPW_OFF  0
#define R0_OFF   1184                 // 1179 rounded up
#define R1_OFF   (R0_OFF + 4585)      // 131*35
#define B2_OFF   (R1_OFF + 8777)      // 131*67
#define B0_OFF   (B2_OFF + 131)
#define B1_OFF   (B0_OFF + 131)
#define W2_OFF   (B1_OFF + 131)
#define PREP_SMEM_FLOATS (W2_OFF + 9 * 144)   // 16235 floats = ~63.4 KB
#define PREP_SMEM_BYTES  (PREP_SMEM_FLOATS * 4)

__global__ void prep_zero_kernel(const float* __restrict__ sp_w,   // (131,9)
                                 const float* __restrict__ rd2_w,  // (131,131)
                                 const float* __restrict__ rd2_b,  // (131)
                                 const float* __restrict__ rd0_w,  // (131,35)
                                 const float* __restrict__ rd0_b,  // (131)
                                 const float* __restrict__ rd1_w,  // (131,67)
                                 const float* __restrict__ rd1_b,  // (131)
                                 const float* __restrict__ rd3_b) {
    if (blockIdx.x > 0) {
        int i = (blockIdx.x - 1) * 256 + threadIdx.x;  // 352*256 = 2*HW/4
        ((float4*)g_GS)[i] = make_float4(0.f, 0.f, 0.f, 0.f);
        return;
    }

    extern __shared__ float dyn[];
    float* spw = dyn + SPW_OFF;   // [c*9 + t]
    float* r0s = dyn + R0_OFF;    // rd0_w linear
    float* r1s = dyn + R1_OFF;    // rd1_w linear
    float* b2s = dyn + B2_OFF;
    float* b0s = dyn + B0_OFF;
    float* b1s = dyn + B1_OFF;
    float* w2s = dyn + W2_OFF;    // [t*144 + j], pads zero

    int tid = threadIdx.x;

    for (int i = tid; i < 1179; i += 256) spw[i] = sp_w[i];
    __syncthreads();

    if (tid < 144) {
        // Stage B: W2 column tid, coalesced row loads of rd2_w
        float acc[9];
#pragma unroll
        for (int t = 0; t < 9; t++) acc[t] = 0.f;
        if (tid < 131) {
#pragma unroll 8
            for (int c = 0; c < 131; c++) {
                float val = rd2_w[c * 131 + tid];
#pragma unroll
                for (int t = 0; t < 9; t++)
                    acc[t] = fmaf(spw[c * 9 + t], val, acc[t]);
            }
        }
#pragma unroll
        for (int t = 0; t < 9; t++) w2s[t * 144 + tid] = acc[t];  // pads = 0
    } else {
        // Prefetch warps: linear, coalesced copies into smem
        int c = tid - 144;  // 0..111
#pragma unroll 4
        for (int i = c; i < 4585; i += 112) r0s[i] = rd0_w[i];
#pragma unroll 4
        for (int i = c; i < 8777; i += 112) r1s[i] = rd1_w[i];
        if (c < 112) {
            for (int i = c; i < 131; i += 112) {
                b2s[i] = rd2_b[i];
                b0s[i] = rd0_b[i];
                b1s[i] = rd1_b[i];
            }
        }
    }
    __syncthreads();

    // Stage C: all from smem.
    // M0 (9 x 36, k<35 real)
    for (int idx = tid; idx < 324; idx += 256) {
        int t = idx / 36, k = idx - t * 36;
        float acc = 0.f;
        if (k < 35) {
#pragma unroll 8
            for (int j = 0; j < 131; j++)
                acc = fmaf(w2s[t * 144 + j], r0s[j * 35 + k], acc);
        }
        g_M0p[idx] = acc;
    }
    // M1 (9 x 72, k<67 real)
    for (int idx = tid; idx < 648; idx += 256) {
        int t = idx / 72, k = idx - t * 72;
        float acc = 0.f;
        if (k < 67) {
#pragma unroll 8
            for (int j = 0; j < 131; j++)
                acc = fmaf(w2s[t * 144 + j], r1s[j * 67 + k], acc);
        }
        g_M1p[idx] = acc;
    }
    // M2 = W2 (pads already zero in w2s)
    for (int idx = tid; idx < 1296; idx += 256) g_M2p[idx] = w2s[idx];

    // swsum / ct per tap (9 threads; smem-only loops)
    if (tid < 9) {
        float s = 0.f, cb = 0.f;
#pragma unroll 4
        for (int c = 0; c < 131; c++) {
            float w = spw[c * 9 + tid];
            s += w;
            cb = fmaf(w, b2s[c], cb);
        }
        float acc = 0.f;
#pragma unroll 4
        for (int j = 0; j < 131; j++)
            acc = fmaf(w2s[tid * 144 + j], b0s[j] + b1s[j], acc);
        g_swsum[tid] = s;
        g_ct[tid] = cb + acc + s * rd3_b[0];  // rd3 bias folded through taps
    }
}

// ---------------------------------------------------------------------------
// gated body: 64-channel partial of G(p), atomic accumulate.
// ---------------------------------------------------------------------------
__device__ __forceinline__ void gated_body(int b, const float* __restrict__ img,
                                           const float* __restrict__ w,
                                           float* sm) {
    int c0 = (b / 176) * 64;
    if (threadIdx.x < 64) sm[threadIdx.x] = w[c0 + threadIdx.x];
    __syncthreads();

    int p4 = (b % 176) * 256 + threadIdx.x;
    const float4* img4 = (const float4*)img + (size_t)c0 * HW4_;
    float4 acc = make_float4(0.f, 0.f, 0.f, 0.f);
#pragma unroll 8
    for (int c = 0; c < 64; c++) {
        float4 v = img4[(size_t)c * HW4_ + p4];
        float wc = sm[c];
        acc.x = fmaf(wc, v.x, acc.x);
        acc.y = fmaf(wc, v.y, acc.y);
        acc.z = fmaf(wc, v.z, acc.z);
        acc.w = fmaf(wc, v.w, acc.w);
    }
    atomicAdd(&g_GS[4 * p4 + 0], acc.x);
    atomicAdd(&g_GS[4 * p4 + 1], acc.y);
    atomicAdd(&g_GS[4 * p4 + 2], acc.z);
    atomicAdd(&g_GS[4 * p4 + 3], acc.w);
}

// ---------------------------------------------------------------------------
// scatter body: G lanes per voxel-group, VPG=2 voxels per group.
// ---------------------------------------------------------------------------
template <int G, int CHN, int LVL>
__device__ __forceinline__ void scatter_body(int b,
                                             const float* __restrict__ feat,
                                             const float* __restrict__ coord,
                                             const int* __restrict__ grid,
                                             int N, float* Ms) {
    constexpr int KP = G * 9;
    constexpr int RES = (9 + G - 1) / G;
    constexpr int VPG = 2;
    constexpr int GROUPS = 256 / G;
    const float* Mglob = (LVL == 0) ? g_M0p : (LVL == 1) ? g_M1p : g_M2p;

    for (int i = threadIdx.x; i < 9 * KP; i += 256) Ms[i] = Mglob[i];
    __syncthreads();

    int lane = threadIdx.x & 31;
    int g = lane & (G - 1);
    int v0 = (b * GROUPS + (int)(threadIdx.x / G)) * VPG;

    float4 e0[VPG], e1[VPG];
    float ec[VPG];
    int cx[VPG], cy[VPG];
    bool act[VPG];
#pragma unroll
    for (int j = 0; j < VPG; j++) {
        int v = v0 + j;
        act[j] = v < N;
        e0[j] = make_float4(0.f, 0.f, 0.f, 0.f);
        e1[j] = make_float4(0.f, 0.f, 0.f, 0.f);
        ec[j] = 0.f;
        cx[j] = 0;
        cy[j] = 0;
        if (act[j]) {
            const float4* f4 = (const float4*)(feat + (size_t)v * CHN + 8 * g);
            e0[j] = f4[0];
            e1[j] = f4[1];
            if (g < 3) ec[j] = coord[(size_t)v * 3 + g];
            cx[j] = grid[2 * v];
            cy[j] = grid[2 * v + 1];
        }
    }

    float res[VPG][RES];
#pragma unroll
    for (int j = 0; j < VPG; j++)
#pragma unroll
        for (int i = 0; i < RES; i++) res[j][i] = 0.f;

#pragma unroll
    for (int t = 0; t < 9; t++) {
        const float* Mrow = Ms + t * KP;
        const float4* M4 = (const float4*)(Mrow + 8 * g);
        float4 m0 = M4[0];
        float4 m1 = M4[1];
        float mc = Mrow[CHN + g];
        float s[VPG];
#pragma unroll
        for (int j = 0; j < VPG; j++) {
            float sj = ec[j] * mc;
            sj = fmaf(m0.x, e0[j].x, sj);
            sj = fmaf(m0.y, e0[j].y, sj);
            sj = fmaf(m0.z, e0[j].z, sj);
            sj = fmaf(m0.w, e0[j].w, sj);
            sj = fmaf(m1.x, e1[j].x, sj);
            sj = fmaf(m1.y, e1[j].y, sj);
            sj = fmaf(m1.z, e1[j].z, sj);
            sj = fmaf(m1.w, e1[j].w, sj);
            s[j] = sj;
        }
#pragma unroll
        for (int o = G / 2; o > 0; o >>= 1) {
#pragma unroll
            for (int j = 0; j < VPG; j++)
                s[j] += __shfl_xor_sync(0xffffffffu, s[j], o);
        }
        if (g == t % G) {
#pragma unroll
            for (int j = 0; j < VPG; j++) res[j][t / G] = s[j];
        }
    }

#pragma unroll
    for (int j = 0; j < VPG; j++) {
        if (act[j]) {
#pragma unroll
            for (int i = 0; i < RES; i++) {
                int t = i * G + g;
                if (t < 9) {
                    int py = cy[j] + 1 - t / 3;
                    int px = cx[j] + 1 - t % 3;
                    if (py >= 0 && py < H_ && px >= 0 && px < W_)
                        atomicAdd(&g_GS[HW_ + py * W_ + px], res[j][i]);
                }
            }
        }
    }
}

// ---------------------------------------------------------------------------
// fused mid: gated (DRAM-bound) + 3 voxel scatters (issue-bound), gated
// interleaved 1-in-6 through the block range.
// ---------------------------------------------------------------------------
__global__ void fused_mid_kernel(const float* __restrict__ img,
                                 const float* __restrict__ rd3_w,
                                 const float* __restrict__ vf0,
                                 const float* __restrict__ vc0,
                                 const int* __restrict__ g0, int N0, int B0,
                                 const float* __restrict__ vf1,
                                 const float* __restrict__ vc1,
                                 const int* __restrict__ g1, int N1, int B1,
                                 const float* __restrict__ vf2,
                                 const float* __restrict__ vc2,
                                 const int* __restrict__ g2, int N2, int SC) {
    __shared__ float sm[9 * 144];
    int b = blockIdx.x;
    int sb;
    if (b < 6 * NB_GATED) {
        int q = b / 6, r = b - q * 6;
        if (r == 0) { gated_body(q, img, rd3_w, sm); return; }
        sb = q * 5 + r - 1;
    } else {
        sb = 5 * NB_GATED + (b - 6 * NB_GATED);
    }
    if (sb >= SC) return;
    if (sb < B0) { scatter_body<4, 32, 0>(sb, vf0, vc0, g0, N0, sm); return; }
    sb -= B0;
    if (sb < B1) { scatter_body<8, 64, 1>(sb, vf1, vc1, g1, N1, sm); return; }
    sb -= B1;
    scatter_body<16, 128, 2>(sb, vf2, vc2, g2, N2, sm);
}

// ---------------------------------------------------------------------------
// final: out[c,p] = img[c,p] * sigmoid(L(p)), sigmoid computed inline from
// g_GS (9-tap halo + sparse term). grid (176,16).
// ---------------------------------------------------------------------------
__global__ void final_kernel(const float* __restrict__ img,
                             float* __restrict__ out,
                             const float* __restrict__ sp_b) {
    __shared__ float ssw[9], sct[9];
    __shared__ float sspb;
    if (threadIdx.x < 9) {
        ssw[threadIdx.x] = g_swsum[threadIdx.x];
        sct[threadIdx.x] = g_ct[threadIdx.x];
    }
    if (threadIdx.x == 9) sspb = sp_b[0];
    __syncthreads();

    int p4 = blockIdx.x * 256 + threadIdx.x;
    int c0 = blockIdx.y * 16;

    float sig[4];
#pragma unroll
    for (int u = 0; u < 4; u++) {
        int p = 4 * p4 + u;
        int y = p / W_, x = p - y * W_;
        float L = sspb + g_GS[HW_ + p];
#pragma unroll
        for (int t = 0; t < 9; t++) {
            int qy = y + t / 3 - 1;
            int qx = x + t % 3 - 1;
            if (qy >= 0 && qy < H_ && qx >= 0 && qx < W_)
                L = fmaf(ssw[t], g_GS[qy * W_ + qx], L + sct[t]);
        }
        sig[u] = 1.f / (1.f + __expf(-L));
    }

    const float4* i4 = (const float4*)img + (size_t)c0 * HW4_ + p4;
    float4* o4 = (float4*)out + (size_t)c0 * HW4_ + p4;
#pragma unroll
    for (int c = 0; c < 16; c++) {
        float4 v = i4[(size_t)c * HW4_];
        float4 o;
        o.x = v.x * sig[0];
        o.y = v.y * sig[1];
        o.z = v.z * sig[2];
        o.w = v.w * sig[3];
        o4[(size_t)c * HW4_] = o;
    }
}

// ---------------------------------------------------------------------------
// Launch
// ---------------------------------------------------------------------------
extern "C" void kernel_launch(void* const* d_in, const int* in_sizes, int n_in,
                              void* d_out, int out_size) {
    const float* img   = (const float*)d_in[0];
    const float* vf0   = (const float*)d_in[1];
    const float* vc0   = (const float*)d_in[2];
    const int*   g0    = (const int*)  d_in[3];
    const float* vf1   = (const float*)d_in[4];
    const float* vc1   = (const float*)d_in[5];
    const int*   g1    = (const int*)  d_in[6];
    const float* vf2   = (const float*)d_in[7];
    const float* vc2   = (const float*)d_in[8];
    const int*   g2    = (const int*)  d_in[9];
    const float* rd0_w = (const float*)d_in[10];
    const float* rd0_b = (const float*)d_in[11];
    const float* rd1_w = (const float*)d_in[12];
    const float* rd1_b = (const float*)d_in[13];
    const float* rd2_w = (const float*)d_in[14];
    const float* rd2_b = (const float*)d_in[15];
    const float* rd3_w = (const float*)d_in[16];
    const float* rd3_b = (const float*)d_in[17];
    const float* sp_w  = (const float*)d_in[18];
    const float* sp_b  = (const float*)d_in[19];

    int N0 = in_sizes[3] / 2;
    int N1 = in_sizes[6] / 2;
    int N2 = in_sizes[9] / 2;
    // VPG=2: voxels per block = 2 * (256/G)
    int B0 = (N0 + 127) / 128;   // G=4  -> 128 voxels/block
    int B1 = (N1 + 63) / 64;     // G=8  -> 64 voxels/block
    int B2 = (N2 + 31) / 32;     // G=16 -> 32 voxels/block
    int SC = B0 + B1 + B2;

    static bool attr_done = false;
    if (!attr_done) {
        cudaFuncSetAttribute(prep_zero_kernel,
                             cudaFuncAttributeMaxDynamicSharedMemorySize,
                             PREP_SMEM_BYTES);
        attr_done = true;
    }

    prep_zero_kernel<<<1 + NB_ZERO, 256, PREP_SMEM_BYTES>>>(
        sp_w, rd2_w, rd2_b, rd0_w, rd0_b, rd1_w, rd1_b, rd3_b);

    fused_mid_kernel<<<NB_GATED + SC, 256>>>(
        img, rd3_w,
        vf0, vc0, g0, N0, B0,
        vf1, vc1, g1, N1, B1,
        vf2, vc2, g2, N2, SC);

    final_kernel<<<dim3(HW4_ / 256, 16), 256>>>(img, (float*)d_out, sp_b);
}

// round 17
// speedup vs baseline: 1.1108x; 1.1055x over previous
#include <cuda_runtime.h>

// Problem constants
#define H_ 256
#define W_ 704
#define HW_ (H_ * W_)          // 180224 = 704 * 256
#define HW4_ (HW_ / 4)         // 45056 = 176 * 256
#define CIMG_ 256
#define NB_GATED 704           // 176 pixel tiles x 4 channel groups
#define NB_PRE 185             // 9 prep blocks + 176 sparse-zero blocks
#define DONE_TARGET 185

// Scratch (device globals — allocation is forbidden).
// Arrays touched through float4 lvalues are DECLARED as float4 — alignment is
// guaranteed by the type, not by attributes or linker luck.
__device__ float4 g_S4[HW4_];        // sparse logit accumulator (HW floats)
__device__ float4 g_Gpart4[HW_];     // gated partial slices (4*HW floats)
__device__ float4 g_SIG4[HW4_];      // per-pixel sigmoid (HW floats)
__device__ float  g_M2p[9 * 144];    // W2 rows, padded (K=131) — scalar access
__device__ float  g_M0p[9 * 36];     // M0 rows, padded (K=35)
__device__ float  g_M1p[9 * 72];     // M1 rows, padded (K=67)
__device__ float  g_swsum[9];
__device__ float  g_ct[9];
__device__ int    g_done;            // prep/zero arrival counter (reset by initL)

#define G_S   ((float*)g_S4)
#define G_GP  ((float*)g_Gpart4)
#define G_SIG ((float*)g_SIG4)

// ---------------------------------------------------------------------------
// prep body: one block per tap t. Folds all 1x1+3x3 weights into per-tap
// composite rows. Scratch comes from the caller's shared array `sm` — this
// kernel must have exactly ONE shared object so the float4 loads on sm in
// scatter_body stay 16B-aligned (R15/R16 crashed on exactly this).
// ---------------------------------------------------------------------------
__device__ void prep_body(int t,
                          const float* __restrict__ sp_w,   // (131,9)
                          const float* __restrict__ rd2_w,  // (131,131)
                          const float* __restrict__ rd2_b,
                          const float* __restrict__ rd0_w,  // (131,35)
                          const float* __restrict__ rd0_b,
                          const float* __restrict__ rd1_w,  // (131,67)
                          const float* __restrict__ rd1_b,
                          const float* __restrict__ rd3_b,
                          float* spw,    // >=131 floats (from sm)
                          float* w2) {   // >=144 floats (from sm)
    int tid = threadIdx.x;

    if (tid < 131) spw[tid] = sp_w[tid * 9 + t];
    __syncthreads();

    // W2 row t: coalesced rd2_w row loads across j
    if (tid < 144) {
        float acc = 0.f;
        if (tid < 131) {
#pragma unroll 8
            for (int c = 0; c < 131; c++)
                acc = fmaf(spw[c], rd2_w[c * 131 + tid], acc);
        }
        w2[tid] = acc;
        g_M2p[t * 144 + tid] = acc;  // pads zero
    }
    __syncthreads();

    if (tid < 36) {
        // M0[t,k] = sum_j W2[t,j] * rd0_w[j,k]
        int k = tid;
        float acc = 0.f;
        if (k < 35) {
#pragma unroll 8
            for (int j = 0; j < 131; j++)
                acc = fmaf(w2[j], rd0_w[j * 35 + k], acc);
        }
        g_M0p[t * 36 + k] = acc;
    } else if (tid >= 64 && tid < 136) {
        // M1[t,k] = sum_j W2[t,j] * rd1_w[j,k]
        int k = tid - 64;
        float acc = 0.f;
        if (k < 67) {
#pragma unroll 8
            for (int j = 0; j < 131; j++)
                acc = fmaf(w2[j], rd1_w[j * 67 + k], acc);
        }
        g_M1p[t * 72 + k] = acc;
    } else if (tid >= 160 && tid < 192) {
        // swsum / ct via one warp (coalesced bias loads + warp reduce)
        int l = tid - 160;
        float s = 0.f, cb = 0.f, ca = 0.f;
        for (int c = l; c < 131; c += 32) {
            float w = spw[c];
            s += w;
            cb = fmaf(w, rd2_b[c], cb);
            ca = fmaf(w2[c], rd0_b[c] + rd1_b[c], ca);
        }
#pragma unroll
        for (int o = 16; o > 0; o >>= 1) {
            s += __shfl_xor_sync(0xffffffffu, s, o);
            cb += __shfl_xor_sync(0xffffffffu, cb, o);
            ca += __shfl_xor_sync(0xffffffffu, ca, o);
        }
        if (l == 0) {
            g_swsum[t] = s;
            g_ct[t] = cb + ca + s * rd3_b[0];  // rd3 bias folded through taps
        }
    }

    // Arrive: fence own stores, block barrier, single counter bump
    __threadfence();
    __syncthreads();
    if (tid == 0) atomicAdd(&g_done, 1);
}

// ---------------------------------------------------------------------------
// gated body: 64-channel partial of G(p) -> plain store into its own slice.
// No atomics, no zero-init (full coverage). Does NOT wait on prep.
// ---------------------------------------------------------------------------
__device__ __forceinline__ void gated_body(int b, const float* __restrict__ img,
                                           const float* __restrict__ w,
                                           float* sm) {
    int slice = b / 176;
    int c0 = slice * 64;
    if (threadIdx.x < 64) sm[threadIdx.x] = w[c0 + threadIdx.x];
    __syncthreads();

    int p4 = (b % 176) * 256 + threadIdx.x;
    const float4* img4 = (const float4*)img + (size_t)c0 * HW4_;
    float4 acc = make_float4(0.f, 0.f, 0.f, 0.f);
#pragma unroll 8
    for (int c = 0; c < 64; c++) {
        float4 v = img4[(size_t)c * HW4_ + p4];
        float wc = sm[c];
        acc.x = fmaf(wc, v.x, acc.x);
        acc.y = fmaf(wc, v.y, acc.y);
        acc.z = fmaf(wc, v.z, acc.z);
        acc.w = fmaf(wc, v.w, acc.w);
    }
    g_Gpart4[(size_t)slice * HW4_ + p4] = acc;
}

// ---------------------------------------------------------------------------
// scatter body: G lanes per voxel-group, VPG=2 voxels per group. Spins until
// prep+zero blocks have arrived (blocks 0..184 are wave-1 residents; safe).
// ---------------------------------------------------------------------------
template <int G, int CHN, int LVL>
__device__ __forceinline__ void scatter_body(int b,
                                             const float* __restrict__ feat,
                                             const float* __restrict__ coord,
                                             const int* __restrict__ grid,
                                             int N, float* Ms) {
    constexpr int KP = G * 9;
    constexpr int RES = (9 + G - 1) / G;
    constexpr int VPG = 2;
    constexpr int GROUPS = 256 / G;
    const float* Mglob = (LVL == 0) ? g_M0p : (LVL == 1) ? g_M1p : g_M2p;

    // Wait for prep + sparse-zero completion
    if (threadIdx.x == 0) {
        while (atomicAdd(&g_done, 0) < DONE_TARGET) __nanosleep(128);
        __threadfence();
    }
    __syncthreads();

    for (int i = threadIdx.x; i < 9 * KP; i += 256) Ms[i] = Mglob[i];
    __syncthreads();

    int lane = threadIdx.x & 31;
    int g = lane & (G - 1);
    int v0 = (b * GROUPS + (int)(threadIdx.x / G)) * VPG;

    float4 e0[VPG], e1[VPG];
    float ec[VPG];
    int cx[VPG], cy[VPG];
    bool act[VPG];
#pragma unroll
    for (int j = 0; j < VPG; j++) {
        int v = v0 + j;
        act[j] = v < N;
        e0[j] = make_float4(0.f, 0.f, 0.f, 0.f);
        e1[j] = make_float4(0.f, 0.f, 0.f, 0.f);
        ec[j] = 0.f;
        cx[j] = 0;
        cy[j] = 0;
        if (act[j]) {
            const float4* f4 = (const float4*)(feat + (size_t)v * CHN + 8 * g);
            e0[j] = f4[0];
            e1[j] = f4[1];
            if (g < 3) ec[j] = coord[(size_t)v * 3 + g];
            cx[j] = grid[2 * v];
            cy[j] = grid[2 * v + 1];
        }
    }

    float res[VPG][RES];
#pragma unroll
    for (int j = 0; j < VPG; j++)
#pragma unroll
        for (int i = 0; i < RES; i++) res[j][i] = 0.f;

#pragma unroll
    for (int t = 0; t < 9; t++) {
        const float* Mrow = Ms + t * KP;
        const float4* M4 = (const float4*)(Mrow + 8 * g);  // sm 16B-aligned
        float4 m0 = M4[0];
        float4 m1 = M4[1];
        float mc = Mrow[CHN + g];
        float s[VPG];
#pragma unroll
        for (int j = 0; j < VPG; j++) {
            float sj = ec[j] * mc;
            sj = fmaf(m0.x, e0[j].x, sj);
            sj = fmaf(m0.y, e0[j].y, sj);
            sj = fmaf(m0.z, e0[j].z, sj);
            sj = fmaf(m0.w, e0[j].w, sj);
            sj = fmaf(m1.x, e1[j].x, sj);
            sj = fmaf(m1.y, e1[j].y, sj);
            sj = fmaf(m1.z, e1[j].z, sj);
            sj = fmaf(m1.w, e1[j].w, sj);
            s[j] = sj;
        }
#pragma unroll
        for (int o = G / 2; o > 0; o >>= 1) {
#pragma unroll
            for (int j = 0; j < VPG; j++)
                s[j] += __shfl_xor_sync(0xffffffffu, s[j], o);
        }
        if (g == t % G) {
#pragma unroll
            for (int j = 0; j < VPG; j++) res[j][t / G] = s[j];
        }
    }

#pragma unroll
    for (int j = 0; j < VPG; j++) {
        if (act[j]) {
#pragma unroll
            for (int i = 0; i < RES; i++) {
                int t = i * G + g;
                if (t < 9) {
                    int py = cy[j] + 1 - t / 3;
                    int px = cx[j] + 1 - t % 3;
                    if (py >= 0 && py < H_ && px >= 0 && px < W_)
                        atomicAdd(&G_S[py * W_ + px], res[j][i]);
                }
            }
        }
    }
}

// ---------------------------------------------------------------------------
// fused mid: blocks [0,9) prep, [9,185) zero sparse accumulator, then gated
// interleaved 1-in-6 with scatter blocks. EXACTLY ONE shared object.
// ---------------------------------------------------------------------------
__global__ void fused_mid_kernel(const float* __restrict__ img,
                                 const float* __restrict__ rd3_w,
                                 const float* __restrict__ vf0,
                                 const float* __restrict__ vc0,
                                 const int* __restrict__ g0, int N0, int B0,
                                 const float* __restrict__ vf1,
                                 const float* __restrict__ vc1,
                                 const int* __restrict__ g1, int N1, int B1,
                                 const float* __restrict__ vf2,
                                 const float* __restrict__ vc2,
                                 const int* __restrict__ g2, int N2, int SC,
                                 const float* __restrict__ sp_w,
                                 const float* __restrict__ rd2_w,
                                 const float* __restrict__ rd2_b,
                                 const float* __restrict__ rd0_w,
                                 const float* __restrict__ rd0_b,
                                 const float* __restrict__ rd1_w,
                                 const float* __restrict__ rd1_b,
                                 const float* __restrict__ rd3_b) {
    __shared__ __align__(16) float sm[9 * 144];
    int b = blockIdx.x;

    if (b < 9) {
        // prep scratch carved from sm: spw = sm[0..131), w2 = sm[144..288)
        prep_body(b, sp_w, rd2_w, rd2_b, rd0_w, rd0_b, rd1_w, rd1_b, rd3_b,
                  sm, sm + 144);
        return;
    }
    if (b < NB_PRE) {
        int i = (b - 9) * 256 + threadIdx.x;  // 176*256 = HW/4 float4s
        g_S4[i] = make_float4(0.f, 0.f, 0.f, 0.f);
        __threadfence();
        __syncthreads();
        if (threadIdx.x == 0) atomicAdd(&g_done, 1);
        return;
    }

    b -= NB_PRE;
    int sb;
    if (b < 6 * NB_GATED) {
        int q = b / 6, r = b - q * 6;
        if (r == 0) { gated_body(q, img, rd3_w, sm); return; }
        sb = q * 5 + r - 1;
    } else {
        sb = 5 * NB_GATED + (b - 6 * NB_GATED);
    }
    if (sb >= SC) return;
    if (sb < B0) { scatter_body<4, 32, 0>(sb, vf0, vc0, g0, N0, sm); return; }
    sb -= B0;
    if (sb < B1) { scatter_body<8, 64, 1>(sb, vf1, vc1, g1, N1, sm); return; }
    sb -= B1;
    scatter_body<16, 128, 2>(sb, vf2, vc2, g2, N2, sm);
}

// ---------------------------------------------------------------------------
// initL: per-pixel logit -> sigmoid. Sums 4 gated slices + sparse + taps.
// Also resets g_done for the next replay.
// ---------------------------------------------------------------------------
__global__ void initL_kernel(const float* __restrict__ sp_b) {
    __shared__ float ssw[9], sct[9];
    if (threadIdx.x < 9) {
        ssw[threadIdx.x] = g_swsum[threadIdx.x];
        sct[threadIdx.x] = g_ct[threadIdx.x];
    }
    if (blockIdx.x == 0 && threadIdx.x == 10) g_done = 0;  // reset for next replay
    __syncthreads();

    int p = blockIdx.x * 256 + threadIdx.x;  // 704*256 = HW exact
    int y = p / W_, x = p - y * W_;
    float L = sp_b[0] + G_S[p];
#pragma unroll
    for (int t = 0; t < 9; t++) {
        int qy = y + t / 3 - 1;
        int qx = x + t % 3 - 1;
        if (qy >= 0 && qy < H_ && qx >= 0 && qx < W_) {
            int q = qy * W_ + qx;
            float Gq = G_GP[q] + G_GP[HW_ + q] +
                       G_GP[2 * HW_ + q] + G_GP[3 * HW_ + q];
            L = fmaf(ssw[t], Gq, L + sct[t]);
        }
    }
    G_SIG[p] = 1.f / (1.f + __expf(-L));
}

// ---------------------------------------------------------------------------
// final: out[c,p] = img[c,p] * sig[p]. grid (176,16), pure float4 stream.
// ---------------------------------------------------------------------------
__global__ void final_kernel(const float* __restrict__ img,
                             float* __restrict__ out) {
    int p4 = blockIdx.x * 256 + threadIdx.x;
    int c0 = blockIdx.y * 16;
    float4 s4 = g_SIG4[p4];
    const float4* i4 = (const float4*)img + (size_t)c0 * HW4_ + p4;
    float4* o4 = (float4*)out + (size_t)c0 * HW4_ + p4;
#pragma unroll
    for (int c = 0; c < 16; c++) {
        float4 v = i4[(size_t)c * HW4_];
        float4 o;
        o.x = v.x * s4.x;
        o.y = v.y * s4.y;
        o.z = v.z * s4.z;
        o.w = v.w * s4.w;
        o4[(size_t)c * HW4_] = o;
    }
}

// ---------------------------------------------------------------------------
// Launch
// ---------------------------------------------------------------------------
extern "C" void kernel_launch(void* const* d_in, const int* in_sizes, int n_in,
                              void* d_out, int out_size) {
    const float* img   = (const float*)d_in[0];
    const float* vf0   = (const float*)d_in[1];
    const float* vc0   = (const float*)d_in[2];
    const int*   g0    = (const int*)  d_in[3];
    const float* vf1   = (const float*)d_in[4];
    const float* vc1   = (const float*)d_in[5];
    const int*   g1    = (const int*)  d_in[6];
    const float* vf2   = (const float*)d_in[7];
    const float* vc2   = (const float*)d_in[8];
    const int*   g2    = (const int*)  d_in[9];
    const float* rd0_w = (const float*)d_in[10];
    const float* rd0_b = (const float*)d_in[11];
    const float* rd1_w = (const float*)d_in[12];
    const float* rd1_b = (const float*)d_in[13];
    const float* rd2_w = (const float*)d_in[14];
    const float* rd2_b = (const float*)d_in[15];
    const float* rd3_w = (const float*)d_in[16];
    const float* rd3_b = (const float*)d_in[17];
    const float* sp_w  = (const float*)d_in[18];
    const float* sp_b  = (const float*)d_in[19];

    int N0 = in_sizes[3] / 2;
    int N1 = in_sizes[6] / 2;
    int N2 = in_sizes[9] / 2;
    // VPG=2: voxels per block = 2 * (256/G)
    int B0 = (N0 + 127) / 128;   // G=4  -> 128 voxels/block
    int B1 = (N1 + 63) / 64;     // G=8  -> 64 voxels/block
    int B2 = (N2 + 31) / 32;     // G=16 -> 32 voxels/block
    int SC = B0 + B1 + B2;

    fused_mid_kernel<<<NB_PRE + NB_GATED + SC, 256>>>(
        img, rd3_w,
        vf0, vc0, g0, N0, B0,
        vf1, vc1, g1, N1, B1,
        vf2, vc2, g2, N2, SC,
        sp_w, rd2_w, rd2_b, rd0_w, rd0_b, rd1_w, rd1_b, rd3_b);

    initL_kernel<<<HW_ / 256, 256>>>(sp_b);

    final_kernel<<<dim3(HW4_ / 256, 16), 256>>>(img, (float*)d_out);
}